// round 10
// baseline (speedup 1.0000x reference)
#include <cuda_runtime.h>
#include <cstdint>
#include <cstddef>

#define N_ATOMS 10000
#define N_PAIRS 250000
#define NP 128
#define NO 128

// Output layout in d_out (floats):
//   [0, 3.84M)      px_new  [N_ATOMS,3,NP]
//   [3.84M, 99.84M) ix      [N_PAIRS,3,NP]
//   [99.84M, ...)   dotted  [N_ATOMS,NO]
#define PXNEW_OFF ((size_t)0)
#define IX_OFF    ((size_t)N_ATOMS * 3 * NP)
#define DOT_OFF   (IX_OFF + (size_t)N_PAIRS * 3 * NP)

// ---- device scratch (allocation-free; zero-initialized at load) ----
__device__ int g_count[N_ATOMS];     // invariant: zero at entry (k_scan restores)
__device__ int g_offset[N_ATOMS + 1];
__device__ int g_pos[N_PAIRS];       // rank of pair within its atom segment
__device__ int g_pairs[N_PAIRS];     // CSR pair ids

// ---------------------------------------------------------------------------
// scatter2: ONE atomic pass = histogram + within-segment rank assignment
__global__ void k_scatter2(const int2* __restrict__ ind2v) {
    int p = blockIdx.x * blockDim.x + threadIdx.x;
    if (p < N_PAIRS) {
        int a = __ldg(&ind2v[p]).x;
        g_pos[p] = atomicAdd(&g_count[a], 1);
    }
}

// exclusive prefix sum over 10000 counts; re-zeroes g_count (self-restoring)
__global__ void k_scan() {
    __shared__ int sb[1024];
    const int CH = 10;
    int t = threadIdx.x;
    int base = t * CH;
    int c[CH];
    int local = 0;
#pragma unroll
    for (int i = 0; i < CH; i++) {
        int idx = base + i;
        c[i] = (idx < N_ATOMS) ? g_count[idx] : 0;
        if (idx < N_ATOMS) g_count[idx] = 0;   // restore zero invariant
        local += c[i];
    }
    sb[t] = local;
    __syncthreads();
    for (int o = 1; o < 1024; o <<= 1) {
        int v = (t >= o) ? sb[t - o] : 0;
        __syncthreads();
        sb[t] += v;
        __syncthreads();
    }
    int run = sb[t] - local;
#pragma unroll
    for (int i = 0; i < CH; i++) {
        int idx = base + i;
        if (idx < N_ATOMS) {
            g_offset[idx] = run;
            run += c[i];
        }
    }
    if (t == 1023) g_offset[N_ATOMS] = sb[1023];
}

// place: atomic-free CSR fill (coalesced reads, cheap scattered 4B writes)
__global__ void k_place(const int2* __restrict__ ind2v) {
    int p = blockIdx.x * blockDim.x + threadIdx.x;
    if (p < N_PAIRS) {
        int a = __ldg(&ind2v[p]).x;
        g_pairs[g_offset[a] + g_pos[p]] = p;
    }
}

// ---------------------------------------------------------------------------
// k_main: block = one atom, 128 threads = 4 warps.
// Phase 1: rank-sort pair ids (deterministic), prefetch j/diff.
// Phase 2: warp y strides pairs by 4, 3x unrolled (12 loads in flight).
// Phase 3: reduce partials, in-block GEMM with w_pp (L1-resident), write out.
#define MAX_SEG 128

__global__ void __launch_bounds__(128, 6)
k_main(const int* __restrict__ ind2,
       const float* __restrict__ px,
       const float* __restrict__ i1,
       const float* __restrict__ diff,
       const float* __restrict__ wpp,
       float* __restrict__ out) {
    __shared__ int   s_pairs[MAX_SEG];
    __shared__ int   s_j[MAX_SEG];
    __shared__ float s_d[3][MAX_SEG];
    __shared__ __align__(16) float s_part[4][3][NP];
    __shared__ __align__(16) float s_fin[3][NP];

    const int a = blockIdx.x;
    const int t = threadIdx.x;
    const int l = t & 31;
    const int y = t >> 5;
    const int q0 = 4 * l;

    const int beg = g_offset[a];
    const int cnt0 = g_offset[a + 1] - beg;
    const int cnt = cnt0 < MAX_SEG ? cnt0 : MAX_SEG;

    // stage pair list into smem (cnt <= 128, one per thread)
    if (t < cnt) s_pairs[t] = g_pairs[beg + t];
    __syncthreads();

    // O(n^2) rank sort (deterministic order; pair ids distinct)
    int v = 0, r = 0;
    if (t < cnt) {
        v = s_pairs[t];
        for (int m = 0; m < cnt; m++) r += (s_pairs[m] < v);
    }
    __syncthreads();
    if (t < cnt) s_pairs[r] = v;
    __syncthreads();

    // prefetch j and diff for the segment (parallel gathers, high MLP)
    if (t < cnt) {
        int pr = s_pairs[t];
        s_j[t]    = __ldg(&ind2[2 * pr + 1]);
        s_d[0][t] = __ldg(&diff[3 * pr + 0]);
        s_d[1][t] = __ldg(&diff[3 * pr + 1]);
        s_d[2][t] = __ldg(&diff[3 * pr + 2]);
    }
    __syncthreads();

    float* out_ix = out + IX_OFF;

    float4 acc0 = make_float4(0.f, 0.f, 0.f, 0.f);
    float4 acc1 = acc0, acc2 = acc0;

    // main pair loop, manually unrolled 3x for MLP (12 loads in flight)
    int k = y;
    for (; k + 8 < cnt; k += 12) {
        int prA = s_pairs[k],     jA = s_j[k];
        int prB = s_pairs[k + 4], jB = s_j[k + 4];
        int prC = s_pairs[k + 8], jC = s_j[k + 8];
        float dA0 = s_d[0][k],     dA1 = s_d[1][k],     dA2 = s_d[2][k];
        float dB0 = s_d[0][k + 4], dB1 = s_d[1][k + 4], dB2 = s_d[2][k + 4];
        float dC0 = s_d[0][k + 8], dC1 = s_d[1][k + 8], dC2 = s_d[2][k + 8];

        float4 sA = __ldcs((const float4*)(i1 + (size_t)prA * NP + q0));
        float4 sB = __ldcs((const float4*)(i1 + (size_t)prB * NP + q0));
        float4 sC = __ldcs((const float4*)(i1 + (size_t)prC * NP + q0));
        const float* pjA = px + (size_t)jA * 3 * NP + q0;
        const float* pjB = px + (size_t)jB * 3 * NP + q0;
        const float* pjC = px + (size_t)jC * 3 * NP + q0;
        float4 a0 = __ldg((const float4*)(pjA));
        float4 a1 = __ldg((const float4*)(pjA + NP));
        float4 a2 = __ldg((const float4*)(pjA + 2 * NP));
        float4 b0 = __ldg((const float4*)(pjB));
        float4 b1 = __ldg((const float4*)(pjB + NP));
        float4 b2 = __ldg((const float4*)(pjB + 2 * NP));
        float4 c0 = __ldg((const float4*)(pjC));
        float4 c1 = __ldg((const float4*)(pjC + NP));
        float4 c2 = __ldg((const float4*)(pjC + 2 * NP));

        float4 vA0, vA1, vA2, vB0, vB1, vB2, vC0, vC1, vC2;
        vA0.x = (a0.x + dA0) * sA.x; vA0.y = (a0.y + dA0) * sA.y;
        vA0.z = (a0.z + dA0) * sA.z; vA0.w = (a0.w + dA0) * sA.w;
        vA1.x = (a1.x + dA1) * sA.x; vA1.y = (a1.y + dA1) * sA.y;
        vA1.z = (a1.z + dA1) * sA.z; vA1.w = (a1.w + dA1) * sA.w;
        vA2.x = (a2.x + dA2) * sA.x; vA2.y = (a2.y + dA2) * sA.y;
        vA2.z = (a2.z + dA2) * sA.z; vA2.w = (a2.w + dA2) * sA.w;
        vB0.x = (b0.x + dB0) * sB.x; vB0.y = (b0.y + dB0) * sB.y;
        vB0.z = (b0.z + dB0) * sB.z; vB0.w = (b0.w + dB0) * sB.w;
        vB1.x = (b1.x + dB1) * sB.x; vB1.y = (b1.y + dB1) * sB.y;
        vB1.z = (b1.z + dB1) * sB.z; vB1.w = (b1.w + dB1) * sB.w;
        vB2.x = (b2.x + dB2) * sB.x; vB2.y = (b2.y + dB2) * sB.y;
        vB2.z = (b2.z + dB2) * sB.z; vB2.w = (b2.w + dB2) * sB.w;
        vC0.x = (c0.x + dC0) * sC.x; vC0.y = (c0.y + dC0) * sC.y;
        vC0.z = (c0.z + dC0) * sC.z; vC0.w = (c0.w + dC0) * sC.w;
        vC1.x = (c1.x + dC1) * sC.x; vC1.y = (c1.y + dC1) * sC.y;
        vC1.z = (c1.z + dC1) * sC.z; vC1.w = (c1.w + dC1) * sC.w;
        vC2.x = (c2.x + dC2) * sC.x; vC2.y = (c2.y + dC2) * sC.y;
        vC2.z = (c2.z + dC2) * sC.z; vC2.w = (c2.w + dC2) * sC.w;

        float* opA = out_ix + (size_t)prA * 3 * NP + q0;
        float* opB = out_ix + (size_t)prB * 3 * NP + q0;
        float* opC = out_ix + (size_t)prC * 3 * NP + q0;
        __stcs((float4*)(opA), vA0);
        __stcs((float4*)(opA + NP), vA1);
        __stcs((float4*)(opA + 2 * NP), vA2);
        __stcs((float4*)(opB), vB0);
        __stcs((float4*)(opB + NP), vB1);
        __stcs((float4*)(opB + 2 * NP), vB2);
        __stcs((float4*)(opC), vC0);
        __stcs((float4*)(opC + NP), vC1);
        __stcs((float4*)(opC + 2 * NP), vC2);

        acc0.x += vA0.x + vB0.x + vC0.x; acc0.y += vA0.y + vB0.y + vC0.y;
        acc0.z += vA0.z + vB0.z + vC0.z; acc0.w += vA0.w + vB0.w + vC0.w;
        acc1.x += vA1.x + vB1.x + vC1.x; acc1.y += vA1.y + vB1.y + vC1.y;
        acc1.z += vA1.z + vB1.z + vC1.z; acc1.w += vA1.w + vB1.w + vC1.w;
        acc2.x += vA2.x + vB2.x + vC2.x; acc2.y += vA2.y + vB2.y + vC2.y;
        acc2.z += vA2.z + vB2.z + vC2.z; acc2.w += vA2.w + vB2.w + vC2.w;
    }
    for (; k < cnt0; k += 4) {
        int pr, j;
        float d0, d1, d2;
        if (k < MAX_SEG) {
            pr = s_pairs[k]; j = s_j[k];
            d0 = s_d[0][k]; d1 = s_d[1][k]; d2 = s_d[2][k];
        } else {  // overflow fallback (never expected for this input)
            pr = g_pairs[beg + k]; j = ind2[2 * pr + 1];
            d0 = diff[3 * pr]; d1 = diff[3 * pr + 1]; d2 = diff[3 * pr + 2];
        }
        float4 s = __ldcs((const float4*)(i1 + (size_t)pr * NP + q0));
        const float* pj = px + (size_t)j * 3 * NP + q0;
        float4 p0 = __ldg((const float4*)(pj));
        float4 p1 = __ldg((const float4*)(pj + NP));
        float4 p2 = __ldg((const float4*)(pj + 2 * NP));

        float4 v0, v1, v2;
        v0.x = (p0.x + d0) * s.x; v0.y = (p0.y + d0) * s.y;
        v0.z = (p0.z + d0) * s.z; v0.w = (p0.w + d0) * s.w;
        v1.x = (p1.x + d1) * s.x; v1.y = (p1.y + d1) * s.y;
        v1.z = (p1.z + d1) * s.z; v1.w = (p1.w + d1) * s.w;
        v2.x = (p2.x + d2) * s.x; v2.y = (p2.y + d2) * s.y;
        v2.z = (p2.z + d2) * s.z; v2.w = (p2.w + d2) * s.w;

        float* op = out_ix + (size_t)pr * 3 * NP + q0;
        __stcs((float4*)(op), v0);
        __stcs((float4*)(op + NP), v1);
        __stcs((float4*)(op + 2 * NP), v2);

        acc0.x += v0.x; acc0.y += v0.y; acc0.z += v0.z; acc0.w += v0.w;
        acc1.x += v1.x; acc1.y += v1.y; acc1.z += v1.z; acc1.w += v1.w;
        acc2.x += v2.x; acc2.y += v2.y; acc2.z += v2.z; acc2.w += v2.w;
    }

    *(float4*)&s_part[y][0][q0] = acc0;
    *(float4*)&s_part[y][1][q0] = acc1;
    *(float4*)&s_part[y][2][q0] = acc2;
    __syncthreads();

    // reduce 4 partials -> s_fin (thread t owns channel t)
    {
        float f0 = s_part[0][0][t] + s_part[1][0][t] + s_part[2][0][t] + s_part[3][0][t];
        float f1 = s_part[0][1][t] + s_part[1][1][t] + s_part[2][1][t] + s_part[3][1][t];
        float f2 = s_part[0][2][t] + s_part[1][2][t] + s_part[2][2][t] + s_part[3][2][t];
        s_fin[0][t] = f0; s_fin[1][t] = f1; s_fin[2][t] = f2;
    }
    __syncthreads();

    // in-block GEMM: px_new[a][x][q] = sum_p s_fin[x][p] * wpp[p][q]
    // thread (l,y): cols q0..q0+3, p-range [32y, 32y+32). wpp is L1-resident.
    float4 o0 = make_float4(0.f, 0.f, 0.f, 0.f);
    float4 o1 = o0, o2 = o0;
#pragma unroll 8
    for (int pp = 0; pp < 32; pp++) {
        int p = (y << 5) + pp;
        float4 w = *(const float4*)&wpp[(size_t)p * NO + q0];
        float a0 = s_fin[0][p], a1 = s_fin[1][p], a2 = s_fin[2][p];
        o0.x += a0 * w.x; o0.y += a0 * w.y; o0.z += a0 * w.z; o0.w += a0 * w.w;
        o1.x += a1 * w.x; o1.y += a1 * w.y; o1.z += a1 * w.z; o1.w += a1 * w.w;
        o2.x += a2 * w.x; o2.y += a2 * w.y; o2.z += a2 * w.z; o2.w += a2 * w.w;
    }
    __syncthreads();   // s_part reuse
    *(float4*)&s_part[y][0][q0] = o0;
    *(float4*)&s_part[y][1][q0] = o1;
    *(float4*)&s_part[y][2][q0] = o2;
    __syncthreads();

    // reduce GEMM partials over y, write px_new and dotted
    {
        float r0 = s_part[0][0][t] + s_part[1][0][t] + s_part[2][0][t] + s_part[3][0][t];
        float r1 = s_part[0][1][t] + s_part[1][1][t] + s_part[2][1][t] + s_part[3][1][t];
        float r2 = s_part[0][2][t] + s_part[1][2][t] + s_part[2][2][t] + s_part[3][2][t];
        float* opx = out + PXNEW_OFF + (size_t)a * 3 * NP + t;
        opx[0]      = r0;
        opx[NP]     = r1;
        opx[2 * NP] = r2;
        out[DOT_OFF + (size_t)a * NO + t] = r0 * r0 + r1 * r1 + r2 * r2;
    }
}

// ---------------------------------------------------------------------------
extern "C" void kernel_launch(void* const* d_in, const int* in_sizes, int n_in,
                              void* d_out, int out_size) {
    const int*   ind2 = (const int*)d_in[0];
    const float* px   = (const float*)d_in[1];
    const float* i1   = (const float*)d_in[2];
    const float* diff = (const float*)d_in[3];
    const float* wpp  = (const float*)d_in[4];
    float* out = (float*)d_out;

    k_scatter2<<<(N_PAIRS + 255) / 256, 256>>>((const int2*)ind2);
    k_scan<<<1, 1024>>>();
    k_place<<<(N_PAIRS + 255) / 256, 256>>>((const int2*)ind2);
    k_main<<<N_ATOMS, 128>>>(ind2, px, i1, diff, wpp, out);
}

// round 11
// speedup vs baseline: 1.1886x; 1.1886x over previous
#include <cuda_runtime.h>
#include <cstdint>
#include <cstddef>

#define N_ATOMS 10000
#define N_PAIRS 250000
#define NP 128
#define NO 128

// Output layout in d_out (floats):
//   [0, 3.84M)      px_new  [N_ATOMS,3,NP]
//   [3.84M, 99.84M) ix      [N_PAIRS,3,NP]
//   [99.84M, ...)   dotted  [N_ATOMS,NO]
#define PXNEW_OFF ((size_t)0)
#define IX_OFF    ((size_t)N_ATOMS * 3 * NP)
#define DOT_OFF   (IX_OFF + (size_t)N_PAIRS * 3 * NP)

#define BCAP 128   // per-atom bucket capacity; P(Poisson(25) >= 128) ~ 1e-45

// ---- device scratch (allocation-free; zero-initialized at load) ----
__device__ int g_cursor[N_ATOMS];           // invariant: zero at entry (k_main end-resets)
__device__ int g_bucket[N_ATOMS][BCAP];

// ---------------------------------------------------------------------------
// single-kernel CSR replacement: scatter pair ids into fixed-capacity buckets
__global__ void k_scatter(const int2* __restrict__ ind2v) {
    int p = blockIdx.x * blockDim.x + threadIdx.x;
    if (p < N_PAIRS) {
        int a = __ldg(&ind2v[p]).x;
        int pos = atomicAdd(&g_cursor[a], 1);
        if (pos < BCAP) g_bucket[a][pos] = p;
    }
}

// ---------------------------------------------------------------------------
// k_main: block = one atom, 128 threads = 4 warps (R9 shape, proven fastest).
// cnt read as uniform broadcast by ALL threads (no single-thread gate, no
// extra syncthreads); cursor reset by one store at block END (no dependency).
// Phase 1: rank-sort bucket (deterministic), prefetch j/diff.
// Phase 2: warp y strides pairs by 4, 2x unrolled (8 loads in flight).
// Phase 3: reduce partials, in-block GEMM with w_pp (L1-resident), write out.
__global__ void __launch_bounds__(128, 8)
k_main(const int* __restrict__ ind2,
       const float* __restrict__ px,
       const float* __restrict__ i1,
       const float* __restrict__ diff,
       const float* __restrict__ wpp,
       float* __restrict__ out) {
    __shared__ int   s_pairs[BCAP];
    __shared__ int   s_j[BCAP];
    __shared__ float s_d[3][BCAP];
    __shared__ __align__(16) float s_part[4][3][NP];
    __shared__ __align__(16) float s_fin[3][NP];

    const int a = blockIdx.x;
    const int t = threadIdx.x;
    const int l = t & 31;
    const int y = t >> 5;
    const int q0 = 4 * l;

    // uniform broadcast read (all threads, same address -> one LDG)
    int c = g_cursor[a];
    const int cnt = c < BCAP ? c : BCAP;

    // stage pair list into smem (cnt <= 128, one per thread)
    if (t < cnt) s_pairs[t] = g_bucket[a][t];
    __syncthreads();

    // O(n^2) rank sort (deterministic order; pair ids distinct)
    int v = 0, r = 0;
    if (t < cnt) {
        v = s_pairs[t];
        for (int m = 0; m < cnt; m++) r += (s_pairs[m] < v);
    }
    __syncthreads();
    if (t < cnt) s_pairs[r] = v;
    __syncthreads();

    // prefetch j and diff for the segment (parallel gathers, high MLP)
    if (t < cnt) {
        int pr = s_pairs[t];
        s_j[t]    = __ldg(&ind2[2 * pr + 1]);
        s_d[0][t] = __ldg(&diff[3 * pr + 0]);
        s_d[1][t] = __ldg(&diff[3 * pr + 1]);
        s_d[2][t] = __ldg(&diff[3 * pr + 2]);
    }
    __syncthreads();

    float* out_ix = out + IX_OFF;

    float4 acc0 = make_float4(0.f, 0.f, 0.f, 0.f);
    float4 acc1 = acc0, acc2 = acc0;

    // main pair loop, manually unrolled 2x for MLP (8 loads in flight)
    int k = y;
    for (; k + 4 < cnt; k += 8) {
        int prA = s_pairs[k],     jA = s_j[k];
        int prB = s_pairs[k + 4], jB = s_j[k + 4];
        float dA0 = s_d[0][k],     dA1 = s_d[1][k],     dA2 = s_d[2][k];
        float dB0 = s_d[0][k + 4], dB1 = s_d[1][k + 4], dB2 = s_d[2][k + 4];

        float4 sA = __ldcs((const float4*)(i1 + (size_t)prA * NP + q0));
        float4 sB = __ldcs((const float4*)(i1 + (size_t)prB * NP + q0));
        const float* pjA = px + (size_t)jA * 3 * NP + q0;
        const float* pjB = px + (size_t)jB * 3 * NP + q0;
        float4 a0 = __ldg((const float4*)(pjA));
        float4 a1 = __ldg((const float4*)(pjA + NP));
        float4 a2 = __ldg((const float4*)(pjA + 2 * NP));
        float4 b0 = __ldg((const float4*)(pjB));
        float4 b1 = __ldg((const float4*)(pjB + NP));
        float4 b2 = __ldg((const float4*)(pjB + 2 * NP));

        float4 vA0, vA1, vA2, vB0, vB1, vB2;
        vA0.x = (a0.x + dA0) * sA.x; vA0.y = (a0.y + dA0) * sA.y;
        vA0.z = (a0.z + dA0) * sA.z; vA0.w = (a0.w + dA0) * sA.w;
        vA1.x = (a1.x + dA1) * sA.x; vA1.y = (a1.y + dA1) * sA.y;
        vA1.z = (a1.z + dA1) * sA.z; vA1.w = (a1.w + dA1) * sA.w;
        vA2.x = (a2.x + dA2) * sA.x; vA2.y = (a2.y + dA2) * sA.y;
        vA2.z = (a2.z + dA2) * sA.z; vA2.w = (a2.w + dA2) * sA.w;
        vB0.x = (b0.x + dB0) * sB.x; vB0.y = (b0.y + dB0) * sB.y;
        vB0.z = (b0.z + dB0) * sB.z; vB0.w = (b0.w + dB0) * sB.w;
        vB1.x = (b1.x + dB1) * sB.x; vB1.y = (b1.y + dB1) * sB.y;
        vB1.z = (b1.z + dB1) * sB.z; vB1.w = (b1.w + dB1) * sB.w;
        vB2.x = (b2.x + dB2) * sB.x; vB2.y = (b2.y + dB2) * sB.y;
        vB2.z = (b2.z + dB2) * sB.z; vB2.w = (b2.w + dB2) * sB.w;

        float* opA = out_ix + (size_t)prA * 3 * NP + q0;
        float* opB = out_ix + (size_t)prB * 3 * NP + q0;
        __stcs((float4*)(opA), vA0);
        __stcs((float4*)(opA + NP), vA1);
        __stcs((float4*)(opA + 2 * NP), vA2);
        __stcs((float4*)(opB), vB0);
        __stcs((float4*)(opB + NP), vB1);
        __stcs((float4*)(opB + 2 * NP), vB2);

        acc0.x += vA0.x + vB0.x; acc0.y += vA0.y + vB0.y;
        acc0.z += vA0.z + vB0.z; acc0.w += vA0.w + vB0.w;
        acc1.x += vA1.x + vB1.x; acc1.y += vA1.y + vB1.y;
        acc1.z += vA1.z + vB1.z; acc1.w += vA1.w + vB1.w;
        acc2.x += vA2.x + vB2.x; acc2.y += vA2.y + vB2.y;
        acc2.z += vA2.z + vB2.z; acc2.w += vA2.w + vB2.w;
    }
    for (; k < cnt; k += 4) {
        int pr = s_pairs[k], j = s_j[k];
        float d0 = s_d[0][k], d1 = s_d[1][k], d2 = s_d[2][k];
        float4 s = __ldcs((const float4*)(i1 + (size_t)pr * NP + q0));
        const float* pj = px + (size_t)j * 3 * NP + q0;
        float4 p0 = __ldg((const float4*)(pj));
        float4 p1 = __ldg((const float4*)(pj + NP));
        float4 p2 = __ldg((const float4*)(pj + 2 * NP));

        float4 v0, v1, v2;
        v0.x = (p0.x + d0) * s.x; v0.y = (p0.y + d0) * s.y;
        v0.z = (p0.z + d0) * s.z; v0.w = (p0.w + d0) * s.w;
        v1.x = (p1.x + d1) * s.x; v1.y = (p1.y + d1) * s.y;
        v1.z = (p1.z + d1) * s.z; v1.w = (p1.w + d1) * s.w;
        v2.x = (p2.x + d2) * s.x; v2.y = (p2.y + d2) * s.y;
        v2.z = (p2.z + d2) * s.z; v2.w = (p2.w + d2) * s.w;

        float* op = out_ix + (size_t)pr * 3 * NP + q0;
        __stcs((float4*)(op), v0);
        __stcs((float4*)(op + NP), v1);
        __stcs((float4*)(op + 2 * NP), v2);

        acc0.x += v0.x; acc0.y += v0.y; acc0.z += v0.z; acc0.w += v0.w;
        acc1.x += v1.x; acc1.y += v1.y; acc1.z += v1.z; acc1.w += v1.w;
        acc2.x += v2.x; acc2.y += v2.y; acc2.z += v2.z; acc2.w += v2.w;
    }

    *(float4*)&s_part[y][0][q0] = acc0;
    *(float4*)&s_part[y][1][q0] = acc1;
    *(float4*)&s_part[y][2][q0] = acc2;
    __syncthreads();

    // reduce 4 partials -> s_fin (thread t owns channel t)
    {
        float f0 = s_part[0][0][t] + s_part[1][0][t] + s_part[2][0][t] + s_part[3][0][t];
        float f1 = s_part[0][1][t] + s_part[1][1][t] + s_part[2][1][t] + s_part[3][1][t];
        float f2 = s_part[0][2][t] + s_part[1][2][t] + s_part[2][2][t] + s_part[3][2][t];
        s_fin[0][t] = f0; s_fin[1][t] = f1; s_fin[2][t] = f2;
    }
    __syncthreads();

    // in-block GEMM: px_new[a][x][q] = sum_p s_fin[x][p] * wpp[p][q]
    // thread (l,y): cols q0..q0+3, p-range [32y, 32y+32). wpp is L1-resident.
    float4 o0 = make_float4(0.f, 0.f, 0.f, 0.f);
    float4 o1 = o0, o2 = o0;
#pragma unroll 8
    for (int pp = 0; pp < 32; pp++) {
        int p = (y << 5) + pp;
        float4 w = *(const float4*)&wpp[(size_t)p * NO + q0];
        float a0 = s_fin[0][p], a1 = s_fin[1][p], a2 = s_fin[2][p];
        o0.x += a0 * w.x; o0.y += a0 * w.y; o0.z += a0 * w.z; o0.w += a0 * w.w;
        o1.x += a1 * w.x; o1.y += a1 * w.y; o1.z += a1 * w.z; o1.w += a1 * w.w;
        o2.x += a2 * w.x; o2.y += a2 * w.y; o2.z += a2 * w.z; o2.w += a2 * w.w;
    }
    __syncthreads();   // s_part reuse
    *(float4*)&s_part[y][0][q0] = o0;
    *(float4*)&s_part[y][1][q0] = o1;
    *(float4*)&s_part[y][2][q0] = o2;
    __syncthreads();

    // reduce GEMM partials over y, write px_new and dotted
    {
        float r0 = s_part[0][0][t] + s_part[1][0][t] + s_part[2][0][t] + s_part[3][0][t];
        float r1 = s_part[0][1][t] + s_part[1][1][t] + s_part[2][1][t] + s_part[3][1][t];
        float r2 = s_part[0][2][t] + s_part[1][2][t] + s_part[2][2][t] + s_part[3][2][t];
        float* opx = out + PXNEW_OFF + (size_t)a * 3 * NP + t;
        opx[0]      = r0;
        opx[NP]     = r1;
        opx[2 * NP] = r2;
        out[DOT_OFF + (size_t)a * NO + t] = r0 * r0 + r1 * r1 + r2 * r2;
    }

    // restore zero invariant for next graph replay (end of block, no sync)
    if (t == 0) g_cursor[a] = 0;
}

// ---------------------------------------------------------------------------
extern "C" void kernel_launch(void* const* d_in, const int* in_sizes, int n_in,
                              void* d_out, int out_size) {
    const int*   ind2 = (const int*)d_in[0];
    const float* px   = (const float*)d_in[1];
    const float* i1   = (const float*)d_in[2];
    const float* diff = (const float*)d_in[3];
    const float* wpp  = (const float*)d_in[4];
    float* out = (float*)d_out;

    k_scatter<<<(N_PAIRS + 255) / 256, 256>>>((const int2*)ind2);
    k_main<<<N_ATOMS, 128>>>(ind2, px, i1, diff, wpp, out);
}